// round 1
// baseline (speedup 1.0000x reference)
#include <cuda_runtime.h>

// ---------------- scratch (device globals; allocation-free) ----------------
#define M_TOK   32768           // B*T
#define N_CODE  8192            // K
#define CDIM    256
#define DDIM    1024
#define TDIM    2048
#define BATCH   16

__device__ float               g_winT [DDIM * CDIM];    // (d, o)  1MB
__device__ float               g_woutT[CDIM * DDIM];    // (c, o)  1MB
__device__ float               g_enc  [M_TOK * CDIM];   // 33.5MB
__device__ float               g_table[N_CODE * DDIM];  // 33.5MB
__device__ float               g_cnorm[N_CODE];
__device__ unsigned long long  g_best [M_TOK];
__device__ int                 g_idx  [M_TOK];

// ---------------- f32x2 helpers (Blackwell FFMA2) ----------------
__device__ __forceinline__ unsigned long long pk2(float x, float y) {
    unsigned long long r;
    asm("mov.b64 %0, {%1, %2};" : "=l"(r)
        : "r"(__float_as_uint(x)), "r"(__float_as_uint(y)));
    return r;
}
__device__ __forceinline__ float2 upk2(unsigned long long v) {
    unsigned int lo, hi;
    asm("mov.b64 {%0, %1}, %2;" : "=r"(lo), "=r"(hi) : "l"(v));
    return make_float2(__uint_as_float(lo), __uint_as_float(hi));
}
#define FMA2(d, a, b) asm("fma.rn.f32x2 %0, %1, %2, %3;" : "=l"(d) : "l"(a), "l"(b), "l"(d))

__device__ __forceinline__ unsigned int ordbits(float f) {
    unsigned int u = __float_as_uint(f);
    return (u & 0x80000000u) ? ~u : (u | 0x80000000u);
}

// ---------------- shared 128x128x16 micro-kernel (8x8/thread, f32x2) -------
// As, Bs: [16][128] float, k-major. ty=tid>>4 rows, tx=tid&15 cols.
__device__ __forceinline__ void mm_step(const float* __restrict__ As,
                                        const float* __restrict__ Bs,
                                        unsigned long long acc[8][4],
                                        int ty, int tx) {
#pragma unroll
    for (int k = 0; k < 16; k++) {
        const float4 a0 = *(const float4*)(As + k * 128 + ty * 8);
        const float4 a1 = *(const float4*)(As + k * 128 + ty * 8 + 4);
        const float4 b0 = *(const float4*)(Bs + k * 128 + tx * 8);
        const float4 b1 = *(const float4*)(Bs + k * 128 + tx * 8 + 4);
        unsigned long long bb0 = pk2(b0.x, b0.y);
        unsigned long long bb1 = pk2(b0.z, b0.w);
        unsigned long long bb2 = pk2(b1.x, b1.y);
        unsigned long long bb3 = pk2(b1.z, b1.w);
        float av[8] = {a0.x, a0.y, a0.z, a0.w, a1.x, a1.y, a1.z, a1.w};
#pragma unroll
        for (int i = 0; i < 8; i++) {
            unsigned long long aa = pk2(av[i], av[i]);
            FMA2(acc[i][0], aa, bb0);
            FMA2(acc[i][1], aa, bb1);
            FMA2(acc[i][2], aa, bb2);
            FMA2(acc[i][3], aa, bb3);
        }
    }
}

// ---------------- prep kernels ----------------
__global__ void prep_win(const float* __restrict__ in_v,
                         const float* __restrict__ in_g) {
    int o = blockIdx.x;  // 0..255
    __shared__ float red[256];
    float s = 0.f;
    for (int d = threadIdx.x; d < DDIM; d += 256) {
        float v = in_v[o * DDIM + d];
        s += v * v;
    }
    red[threadIdx.x] = s;
    __syncthreads();
    for (int st = 128; st; st >>= 1) {
        if (threadIdx.x < st) red[threadIdx.x] += red[threadIdx.x + st];
        __syncthreads();
    }
    float scale = in_g[o] * rsqrtf(red[0]);
    for (int d = threadIdx.x; d < DDIM; d += 256)
        g_winT[d * CDIM + o] = in_v[o * DDIM + d] * scale;
}

__global__ void prep_wout(const float* __restrict__ out_v,
                          const float* __restrict__ out_g) {
    int o = blockIdx.x;  // 0..1023
    __shared__ float red[256];
    float v = out_v[o * CDIM + threadIdx.x];
    red[threadIdx.x] = v * v;
    __syncthreads();
    for (int st = 128; st; st >>= 1) {
        if (threadIdx.x < st) red[threadIdx.x] += red[threadIdx.x + st];
        __syncthreads();
    }
    float scale = out_g[o] * rsqrtf(red[0]);
    g_woutT[threadIdx.x * DDIM + o] = v * scale;
}

__global__ void prep_cnorm(const float* __restrict__ cb) {
    int k = blockIdx.x;  // 0..8191
    __shared__ float red[256];
    float v = cb[k * CDIM + threadIdx.x];
    red[threadIdx.x] = v * v;
    __syncthreads();
    for (int st = 128; st; st >>= 1) {
        if (threadIdx.x < st) red[threadIdx.x] += red[threadIdx.x + st];
        __syncthreads();
    }
    if (threadIdx.x == 0) g_cnorm[k] = red[0];
}

__global__ void init_best() {
    int m = blockIdx.x * 256 + threadIdx.x;
    if (m < M_TOK) g_best[m] = 0xFFFFFFFFFFFFFFFFull;
}

// ---------------- GEMM 1: enc = z^T @ w_inT + in_b ----------------
// per batch: M=T (rows=t, contiguous in z), N=CD tile, K=D
__global__ void __launch_bounds__(256, 2)
gemm_ze(const float* __restrict__ z, const float* __restrict__ in_b) {
    __shared__ __align__(16) float As[16 * 128];
    __shared__ __align__(16) float Bs[16 * 128];
    int bx = blockIdx.x;  // o tile (0..1)
    int by = blockIdx.y;  // t tile (0..15)
    int b  = blockIdx.z;  // batch
    int tid = threadIdx.x, tx = tid & 15, ty = tid >> 4;

    unsigned long long acc[8][4];
#pragma unroll
    for (int i = 0; i < 8; i++)
#pragma unroll
        for (int j = 0; j < 4; j++) acc[i][j] = 0ull;

    const float* zb = z + (size_t)b * DDIM * TDIM + by * 128;  // + d*TDIM + m
    const float* wb = g_winT + bx * 128;                        // + d*CDIM + n

    for (int k0 = 0; k0 < DDIM; k0 += 16) {
#pragma unroll
        for (int it = 0; it < 2; it++) {
            int e  = tid + it * 256;
            int k  = e >> 5;
            int m4 = (e & 31) * 4;
            *(float4*)&As[k * 128 + m4] =
                *(const float4*)(zb + (size_t)(k0 + k) * TDIM + m4);
            *(float4*)&Bs[k * 128 + m4] =
                *(const float4*)(wb + (size_t)(k0 + k) * CDIM + m4);
        }
        __syncthreads();
        mm_step(As, Bs, acc, ty, tx);
        __syncthreads();
    }

    int nbase = bx * 128 + tx * 8;
    float bias[8];
#pragma unroll
    for (int j = 0; j < 8; j++) bias[j] = in_b[nbase + j];
#pragma unroll
    for (int i = 0; i < 8; i++) {
        int row = b * TDIM + by * 128 + ty * 8 + i;
        float* dst = g_enc + (size_t)row * CDIM + nbase;
        float2 v0 = upk2(acc[i][0]), v1 = upk2(acc[i][1]);
        float2 v2 = upk2(acc[i][2]), v3 = upk2(acc[i][3]);
        float4 w0 = make_float4(v0.x + bias[0], v0.y + bias[1],
                                v1.x + bias[2], v1.y + bias[3]);
        float4 w1 = make_float4(v2.x + bias[4], v2.y + bias[5],
                                v3.x + bias[6], v3.y + bias[7]);
        *(float4*)dst       = w0;
        *(float4*)(dst + 4) = w1;
    }
}

// ---------------- GEMM 2: distance + fused argmin ----------------
// M=32768 tokens, N=8192 codes, K=256; dist = cnorm[n] - 2*enc.cb
__global__ void __launch_bounds__(256, 2)
gemm_dist(const float* __restrict__ cb) {
    __shared__ __align__(16) float As[16 * 128];
    __shared__ __align__(16) float Bs[16 * 128];
    int bx = blockIdx.x;  // code tile (0..63)
    int by = blockIdx.y;  // token tile (0..255)
    int tid = threadIdx.x, tx = tid & 15, ty = tid >> 4;

    unsigned long long acc[8][4];
#pragma unroll
    for (int i = 0; i < 8; i++)
#pragma unroll
        for (int j = 0; j < 4; j++) acc[i][j] = 0ull;

    const float* Ab = g_enc + (size_t)(by * 128) * CDIM;
    const float* Bb = cb    + (size_t)(bx * 128) * CDIM;

    for (int k0 = 0; k0 < CDIM; k0 += 16) {
#pragma unroll
        for (int it = 0; it < 2; it++) {
            int e  = tid + it * 256;
            int r  = e >> 2;
            int kf = (e & 3) * 4;
            float4 va = *(const float4*)(Ab + (size_t)r * CDIM + k0 + kf);
            As[(kf + 0) * 128 + r] = va.x;
            As[(kf + 1) * 128 + r] = va.y;
            As[(kf + 2) * 128 + r] = va.z;
            As[(kf + 3) * 128 + r] = va.w;
            float4 vb = *(const float4*)(Bb + (size_t)r * CDIM + k0 + kf);
            Bs[(kf + 0) * 128 + r] = vb.x;
            Bs[(kf + 1) * 128 + r] = vb.y;
            Bs[(kf + 2) * 128 + r] = vb.z;
            Bs[(kf + 3) * 128 + r] = vb.w;
        }
        __syncthreads();
        mm_step(As, Bs, acc, ty, tx);
        __syncthreads();
    }

    int colbase = bx * 128 + tx * 8;
    float cn[8];
#pragma unroll
    for (int j = 0; j < 8; j++) cn[j] = g_cnorm[colbase + j];

#pragma unroll
    for (int i = 0; i < 8; i++) {
        int grow = by * 128 + ty * 8 + i;
        unsigned long long best = 0xFFFFFFFFFFFFFFFFull;
#pragma unroll
        for (int jj = 0; jj < 4; jj++) {
            float2 v = upk2(acc[i][jj]);
            float d0 = cn[2 * jj]     - 2.f * v.x;
            float d1 = cn[2 * jj + 1] - 2.f * v.y;
            unsigned long long p0 =
                ((unsigned long long)ordbits(d0) << 32) | (unsigned int)(colbase + 2 * jj);
            unsigned long long p1 =
                ((unsigned long long)ordbits(d1) << 32) | (unsigned int)(colbase + 2 * jj + 1);
            if (p0 < best) best = p0;
            if (p1 < best) best = p1;
        }
#pragma unroll
        for (int off = 8; off; off >>= 1) {
            unsigned long long o = __shfl_down_sync(0xFFFFFFFFu, best, off, 16);
            if (o < best) best = o;
        }
        if (tx == 0) atomicMin(&g_best[grow], best);
    }
}

// ---------------- GEMM 3: table = codebook @ w_outT ----------------
// M=8192 codes, N=1024 (o), K=256 (c)
__global__ void __launch_bounds__(256, 2)
gemm_table(const float* __restrict__ cb) {
    __shared__ __align__(16) float As[16 * 128];
    __shared__ __align__(16) float Bs[16 * 128];
    int bx = blockIdx.x;  // o tile (0..7)
    int by = blockIdx.y;  // code tile (0..63)
    int tid = threadIdx.x, tx = tid & 15, ty = tid >> 4;

    unsigned long long acc[8][4];
#pragma unroll
    for (int i = 0; i < 8; i++)
#pragma unroll
        for (int j = 0; j < 4; j++) acc[i][j] = 0ull;

    const float* Ab = cb + (size_t)(by * 128) * CDIM;   // transpose-load
    const float* Bb = g_woutT + bx * 128;               // + c*DDIM + n

    for (int k0 = 0; k0 < CDIM; k0 += 16) {
#pragma unroll
        for (int it = 0; it < 2; it++) {
            int e  = tid + it * 256;
            int r  = e >> 2;
            int kf = (e & 3) * 4;
            float4 va = *(const float4*)(Ab + (size_t)r * CDIM + k0 + kf);
            As[(kf + 0) * 128 + r] = va.x;
            As[(kf + 1) * 128 + r] = va.y;
            As[(kf + 2) * 128 + r] = va.z;
            As[(kf + 3) * 128 + r] = va.w;
            int k  = e >> 5;
            int n4 = (e & 31) * 4;
            *(float4*)&Bs[k * 128 + n4] =
                *(const float4*)(Bb + (size_t)(k0 + k) * DDIM + n4);
        }
        __syncthreads();
        mm_step(As, Bs, acc, ty, tx);
        __syncthreads();
    }

    int nbase = bx * 128 + tx * 8;
#pragma unroll
    for (int i = 0; i < 8; i++) {
        int row = by * 128 + ty * 8 + i;
        float* dst = g_table + (size_t)row * DDIM + nbase;
        float2 v0 = upk2(acc[i][0]), v1 = upk2(acc[i][1]);
        float2 v2 = upk2(acc[i][2]), v3 = upk2(acc[i][3]);
        *(float4*)dst       = make_float4(v0.x, v0.y, v1.x, v1.y);
        *(float4*)(dst + 4) = make_float4(v2.x, v2.y, v3.x, v3.y);
    }
}

// ---------------- indices extraction ----------------
__global__ void extract_idx(float* __restrict__ out_idx) {
    int m = blockIdx.x * 256 + threadIdx.x;
    if (m >= M_TOK) return;
    int id = (int)(unsigned int)(g_best[m] & 0xFFFFFFFFull);
    g_idx[m] = id;
    if (out_idx) out_idx[m] = (float)id;
}

// ---------------- gather: out[b,o,t] = table[idx[b,t]][o] + out_b[o] -------
__global__ void gather_out(const float* __restrict__ out_b,
                           float* __restrict__ out) {
    int b  = blockIdx.y;
    int t0 = blockIdx.x * 64;
    __shared__ float sm[64][65];
    __shared__ int sidx[64];
    int tid = threadIdx.x;
    if (tid < 64) sidx[tid] = g_idx[b * TDIM + t0 + tid];
    __syncthreads();

    for (int o0 = 0; o0 < DDIM; o0 += 64) {
#pragma unroll
        for (int p = 0; p < 16; p++) {
            int e  = tid + p * 256;
            int tl = e >> 6, ol = e & 63;
            sm[tl][ol] = g_table[(size_t)sidx[tl] * DDIM + o0 + ol];
        }
        __syncthreads();
#pragma unroll
        for (int p = 0; p < 16; p++) {
            int e  = tid + p * 256;
            int ol = e >> 6, tl = e & 63;
            out[(size_t)b * DDIM * TDIM + (size_t)(o0 + ol) * TDIM + t0 + tl] =
                sm[tl][ol] + out_b[o0 + ol];
        }
        __syncthreads();
    }
}

// ---------------- launch ----------------
extern "C" void kernel_launch(void* const* d_in, const int* in_sizes, int n_in,
                              void* d_out, int out_size) {
    const float* z     = (const float*)d_in[0];
    const float* in_v  = (const float*)d_in[1];
    const float* in_g  = (const float*)d_in[2];
    const float* in_b  = (const float*)d_in[3];
    const float* out_v = (const float*)d_in[4];
    const float* out_g = (const float*)d_in[5];
    const float* out_b = (const float*)d_in[6];
    const float* cbk   = (const float*)d_in[7];
    float* out = (float*)d_out;

    prep_win  <<<256, 256>>>(in_v, in_g);
    prep_wout <<<1024, 256>>>(out_v, out_g);
    prep_cnorm<<<N_CODE, 256>>>(cbk);
    init_best <<<M_TOK / 256, 256>>>();

    gemm_ze   <<<dim3(2, 16, BATCH), 256>>>(z, in_b);
    gemm_table<<<dim3(8, 64), 256>>>(cbk);
    gemm_dist <<<dim3(64, 256), 256>>>(cbk);

    const long long out_elems = (long long)BATCH * DDIM * TDIM;  // 33554432
    float* idx_dst = (out_size >= out_elems + M_TOK) ? out + out_elems : nullptr;
    extract_idx<<<M_TOK / 256, 256>>>(idx_dst);

    gather_out<<<dim3(TDIM / 64, BATCH), 256>>>(out_b, out);
}

// round 3
// speedup vs baseline: 2.7043x; 2.7043x over previous
#include <cuda_runtime.h>
#include <cuda_fp16.h>
#include <cstdint>

#define M_TOK   32768
#define N_CODE  8192
#define CDIM    256
#define DDIM    1024
#define TDIM    2048
#define BATCH   16

// ---------------- device scratch ----------------
__device__ float               g_winT [DDIM * CDIM];
__device__ float               g_woutT[CDIM * DDIM];
__device__ float               g_table[N_CODE * DDIM];
__device__ float               g_cnorm[N_CODE];
__device__ float               g_enc  [M_TOK * CDIM];        // fp32 enc (exact rerank)
__device__ __half              g_encH [M_TOK * CDIM];        // fp16 enc (coarse)
__device__ __half              g_cbH  [N_CODE * CDIM];       // fp16 codebook
__device__ unsigned long long  g_part [(size_t)M_TOK * 512]; // per-token 256 groups x top2
__device__ int                 g_idx  [M_TOK];

// ---------------- helpers ----------------
__device__ __forceinline__ uint32_t smem_u32(const void* p) {
    uint32_t a;
    asm("{ .reg .u64 t; cvta.to.shared.u64 t, %1; cvt.u32.u64 %0, t; }" : "=r"(a) : "l"(p));
    return a;
}
__device__ __forceinline__ unsigned int ordbits(float f) {
    unsigned int u = __float_as_uint(f);
    return (u & 0x80000000u) ? ~u : (u | 0x80000000u);
}
__device__ __forceinline__ unsigned long long u64min(unsigned long long a, unsigned long long b) {
    return a < b ? a : b;
}
__device__ __forceinline__ unsigned long long u64max(unsigned long long a, unsigned long long b) {
    return a > b ? a : b;
}

// f32x2 (Blackwell FFMA2) for the fp32 GEMMs
__device__ __forceinline__ unsigned long long pk2(float x, float y) {
    unsigned long long r;
    asm("mov.b64 %0, {%1, %2};" : "=l"(r) : "r"(__float_as_uint(x)), "r"(__float_as_uint(y)));
    return r;
}
__device__ __forceinline__ float2 upk2(unsigned long long v) {
    unsigned int lo, hi;
    asm("mov.b64 {%0, %1}, %2;" : "=r"(lo), "=r"(hi) : "l"(v));
    return make_float2(__uint_as_float(lo), __uint_as_float(hi));
}
#define FMA2(d, a, b) asm("fma.rn.f32x2 %0, %1, %2, %3;" : "=l"(d) : "l"(a), "l"(b), "l"(d))

// mma / ldmatrix / cp.async (all non-'a' PTX, sm_80+/75+)
#define LDSM_X4(r0, r1, r2, r3, addr) \
    asm volatile("ldmatrix.sync.aligned.m8n8.x4.shared.b16 {%0,%1,%2,%3}, [%4];" \
                 : "=r"(r0), "=r"(r1), "=r"(r2), "=r"(r3) : "r"(addr))
#define LDSM_X2(r0, r1, addr) \
    asm volatile("ldmatrix.sync.aligned.m8n8.x2.shared.b16 {%0,%1}, [%2];" \
                 : "=r"(r0), "=r"(r1) : "r"(addr))
#define MMA16816(c, a, b) \
    asm volatile("mma.sync.aligned.m16n8k16.row.col.f32.f16.f16.f32 " \
                 "{%0,%1,%2,%3},{%4,%5,%6,%7},{%8,%9},{%0,%1,%2,%3};" \
                 : "+f"((c)[0]), "+f"((c)[1]), "+f"((c)[2]), "+f"((c)[3]) \
                 : "r"((a)[0]), "r"((a)[1]), "r"((a)[2]), "r"((a)[3]), \
                   "r"((b)[0]), "r"((b)[1]))
#define CP_ASYNC16(dst, src) \
    asm volatile("cp.async.cg.shared.global [%0], [%1], 16;" :: "r"(dst), "l"(src))
#define CP_COMMIT() asm volatile("cp.async.commit_group;")
#define CP_WAIT1()  asm volatile("cp.async.wait_group 1;")
#define CP_WAIT0()  asm volatile("cp.async.wait_group 0;")

// ---------------- fp32 FFMA2 micro-kernel ----------------
__device__ __forceinline__ void mm_step(const float* __restrict__ As,
                                        const float* __restrict__ Bs,
                                        unsigned long long acc[8][4],
                                        int ty, int tx) {
#pragma unroll
    for (int k = 0; k < 16; k++) {
        const float4 a0 = *(const float4*)(As + k * 128 + ty * 8);
        const float4 a1 = *(const float4*)(As + k * 128 + ty * 8 + 4);
        const float4 b0 = *(const float4*)(Bs + k * 128 + tx * 8);
        const float4 b1 = *(const float4*)(Bs + k * 128 + tx * 8 + 4);
        unsigned long long bb0 = pk2(b0.x, b0.y);
        unsigned long long bb1 = pk2(b0.z, b0.w);
        unsigned long long bb2 = pk2(b1.x, b1.y);
        unsigned long long bb3 = pk2(b1.z, b1.w);
        float av[8] = {a0.x, a0.y, a0.z, a0.w, a1.x, a1.y, a1.z, a1.w};
#pragma unroll
        for (int i = 0; i < 8; i++) {
            unsigned long long aa = pk2(av[i], av[i]);
            FMA2(acc[i][0], aa, bb0);
            FMA2(acc[i][1], aa, bb1);
            FMA2(acc[i][2], aa, bb2);
            FMA2(acc[i][3], aa, bb3);
        }
    }
}

// ---------------- prep kernels ----------------
__global__ void prep_win(const float* __restrict__ in_v, const float* __restrict__ in_g) {
    int o = blockIdx.x;
    __shared__ float red[256];
    float s = 0.f;
    for (int d = threadIdx.x; d < DDIM; d += 256) {
        float v = in_v[o * DDIM + d];
        s += v * v;
    }
    red[threadIdx.x] = s;
    __syncthreads();
    for (int st = 128; st; st >>= 1) {
        if (threadIdx.x < st) red[threadIdx.x] += red[threadIdx.x + st];
        __syncthreads();
    }
    float scale = in_g[o] * rsqrtf(red[0]);
    for (int d = threadIdx.x; d < DDIM; d += 256)
        g_winT[d * CDIM + o] = in_v[o * DDIM + d] * scale;
}

__global__ void prep_wout(const float* __restrict__ out_v, const float* __restrict__ out_g) {
    int o = blockIdx.x;
    __shared__ float red[256];
    float v = out_v[o * CDIM + threadIdx.x];
    red[threadIdx.x] = v * v;
    __syncthreads();
    for (int st = 128; st; st >>= 1) {
        if (threadIdx.x < st) red[threadIdx.x] += red[threadIdx.x + st];
        __syncthreads();
    }
    float scale = out_g[o] * rsqrtf(red[0]);
    g_woutT[threadIdx.x * DDIM + o] = v * scale;
}

__global__ void prep_cnorm(const float* __restrict__ cb) {
    int k = blockIdx.x;
    __shared__ float red[256];
    float v = cb[k * CDIM + threadIdx.x];
    red[threadIdx.x] = v * v;
    __syncthreads();
    for (int st = 128; st; st >>= 1) {
        if (threadIdx.x < st) red[threadIdx.x] += red[threadIdx.x + st];
        __syncthreads();
    }
    if (threadIdx.x == 0) g_cnorm[k] = red[0];
}

__global__ void conv_cbH(const float* __restrict__ cb) {
    int i = blockIdx.x * 256 + threadIdx.x;
    g_cbH[i] = __float2half_rn(cb[i]);
}

// ---------------- GEMM 1: enc = z^T @ w_inT + in_b (fp32 + fp16 copies) -----
__global__ void __launch_bounds__(256, 2)
gemm_ze(const float* __restrict__ z, const float* __restrict__ in_b) {
    __shared__ __align__(16) float As[16 * 128];
    __shared__ __align__(16) float Bs[16 * 128];
    int bx = blockIdx.x;  // CD tile (0..1)
    int by = blockIdx.y;  // t tile (0..15)
    int b  = blockIdx.z;
    int tid = threadIdx.x, tx = tid & 15, ty = tid >> 4;

    unsigned long long acc[8][4];
#pragma unroll
    for (int i = 0; i < 8; i++)
#pragma unroll
        for (int j = 0; j < 4; j++) acc[i][j] = 0ull;

    const float* zb = z + (size_t)b * DDIM * TDIM + by * 128;
    const float* wb = g_winT + bx * 128;

    for (int k0 = 0; k0 < DDIM; k0 += 16) {
#pragma unroll
        for (int it = 0; it < 2; it++) {
            int e  = tid + it * 256;
            int k  = e >> 5;
            int m4 = (e & 31) * 4;
            *(float4*)&As[k * 128 + m4] = *(const float4*)(zb + (size_t)(k0 + k) * TDIM + m4);
            *(float4*)&Bs[k * 128 + m4] = *(const float4*)(wb + (size_t)(k0 + k) * CDIM + m4);
        }
        __syncthreads();
        mm_step(As, Bs, acc, ty, tx);
        __syncthreads();
    }

    int nbase = bx * 128 + tx * 8;
    float bias[8];
#pragma unroll
    for (int j = 0; j < 8; j++) bias[j] = in_b[nbase + j];
#pragma unroll
    for (int i = 0; i < 8; i++) {
        int row = b * TDIM + by * 128 + ty * 8 + i;
        float2 v0 = upk2(acc[i][0]), v1 = upk2(acc[i][1]);
        float2 v2 = upk2(acc[i][2]), v3 = upk2(acc[i][3]);
        float vals[8] = {v0.x + bias[0], v0.y + bias[1], v1.x + bias[2], v1.y + bias[3],
                         v2.x + bias[4], v2.y + bias[5], v3.x + bias[6], v3.y + bias[7]};
        float* dst = g_enc + (size_t)row * CDIM + nbase;
        *(float4*)dst       = make_float4(vals[0], vals[1], vals[2], vals[3]);
        *(float4*)(dst + 4) = make_float4(vals[4], vals[5], vals[6], vals[7]);
        __half h[8];
#pragma unroll
        for (int j = 0; j < 8; j++) h[j] = __float2half_rn(vals[j]);
        *(uint4*)(g_encH + (size_t)row * CDIM + nbase) = *(uint4*)h;
    }
}

// ---------------- coarse distance: fp16 mma.sync + top2-per-32-codes --------
// grid (64 code tiles, 256 token tiles), 256 threads, dyn smem = 3*32KB
__global__ void __launch_bounds__(256, 1)
coarse_dist() {
    extern __shared__ __align__(128) char sm[];
    const int tid = threadIdx.x, lane = tid & 31, wid = tid >> 5;
    const int wm = wid >> 2, wn = wid & 3;   // 2 x 4 warps -> warp tile 64x32
    const int bx = blockIdx.x, by = blockIdx.y;
    uint32_t smb = smem_u32(sm);

    float c[4][4][4];
#pragma unroll
    for (int mt = 0; mt < 4; mt++)
#pragma unroll
        for (int nt = 0; nt < 4; nt++)
#pragma unroll
            for (int q = 0; q < 4; q++) c[mt][nt][q] = 0.f;

    const char* baseA = (const char*)g_encH + (size_t)(by * 128) * 512;
    const char* baseB = (const char*)g_cbH  + (size_t)(bx * 128) * 512;

#define ISSUE_CHUNK(chunk, stage) do {                                           \
    uint32_t dA = smb + (stage) * 32768u;                                        \
    uint32_t dB = dA + 16384u;                                                   \
    _Pragma("unroll")                                                            \
    for (int i_ = 0; i_ < 4; i_++) {                                             \
        int e_ = tid + i_ * 256;                                                 \
        int row_ = e_ >> 3, cc_ = e_ & 7;                                        \
        uint32_t sw_ = (uint32_t)((cc_ ^ (row_ & 7)) * 16);                      \
        CP_ASYNC16(dA + row_ * 128 + sw_,                                        \
                   baseA + (size_t)row_ * 512 + (chunk) * 128 + cc_ * 16);       \
        CP_ASYNC16(dB + row_ * 128 + sw_,                                        \
                   baseB + (size_t)row_ * 512 + (chunk) * 128 + cc_ * 16);       \
    }                                                                            \
    CP_COMMIT();                                                                 \
} while (0)

    ISSUE_CHUNK(0, 0);
    ISSUE_CHUNK(1, 1);

    const int rA  = wm * 64 + (lane & 15);
    const int khA = lane >> 4;
    const int nB  = wn * 32 + (lane & 7);
    const int khB = (lane >> 3) & 1;

    for (int ch = 0; ch < 4; ch++) {
        int st = ch % 3;
        if (ch == 3) { CP_WAIT0(); } else { CP_WAIT1(); }
        __syncthreads();
        if (ch + 2 < 4) ISSUE_CHUNK(ch + 2, (ch + 2) % 3);

        uint32_t Ab = smb + st * 32768u;
        uint32_t Bb = Ab + 16384u;
#pragma unroll
        for (int kt = 0; kt < 4; kt++) {
            uint32_t a[4][4], bfr[4][2];
#pragma unroll
            for (int mt = 0; mt < 4; mt++) {
                uint32_t ad = Ab + (rA + mt * 16) * 128
                            + (uint32_t)((((kt * 2 + khA) ^ (rA & 7))) * 16);
                LDSM_X4(a[mt][0], a[mt][1], a[mt][2], a[mt][3], ad);
            }
#pragma unroll
            for (int nt = 0; nt < 4; nt++) {
                uint32_t bd = Bb + (nB + nt * 8) * 128
                            + (uint32_t)((((kt * 2 + khB) ^ (nB & 7))) * 16);
                LDSM_X2(bfr[nt][0], bfr[nt][1], bd);
            }
#pragma unroll
            for (int mt = 0; mt < 4; mt++)
#pragma unroll
                for (int nt = 0; nt < 4; nt++) MMA16816(c[mt][nt], a[mt], bfr[nt]);
        }
    }

    // epilogue: per-row top2 within this warp's 32 columns
#pragma unroll
    for (int mt = 0; mt < 4; mt++) {
#pragma unroll
        for (int h = 0; h < 2; h++) {
            unsigned long long b1 = ~0ull, b2 = ~0ull;
#pragma unroll
            for (int nt = 0; nt < 4; nt++) {
#pragma unroll
                for (int j = 0; j < 2; j++) {
                    int col = bx * 128 + wn * 32 + nt * 8 + (lane & 3) * 2 + j;
                    float d = g_cnorm[col] - 2.f * c[mt][nt][h * 2 + j];
                    unsigned long long p =
                        ((unsigned long long)ordbits(d) << 32) | (unsigned)col;
                    if (p < b1) { b2 = b1; b1 = p; }
                    else if (p < b2) { b2 = p; }
                }
            }
#pragma unroll
            for (int x = 1; x <= 2; x <<= 1) {
                unsigned long long o1 = __shfl_xor_sync(0xFFFFFFFFu, b1, x);
                unsigned long long o2 = __shfl_xor_sync(0xFFFFFFFFu, b2, x);
                unsigned long long w1 = u64min(b1, o1);
                unsigned long long l1 = u64max(b1, o1);
                b2 = u64min(l1, u64min(b2, o2));
                b1 = w1;
            }
            if ((lane & 3) == 0) {
                int token = by * 128 + wm * 64 + mt * 16 + (lane >> 2) + h * 8;
                int g = bx * 4 + wn;
                g_part[(size_t)token * 512 + g * 2 + 0] = b1;
                g_part[(size_t)token * 512 + g * 2 + 1] = b2;
            }
        }
    }
#undef ISSUE_CHUNK
}

// ---------------- select: coarse min + margin + exact rerank ----------------
__global__ void __launch_bounds__(256)
select_k(const float* __restrict__ cbk, float* __restrict__ out_idx) {
    __shared__ int s_cnt[8];
    __shared__ unsigned s_code[8][64];
    int w = threadIdx.x >> 5, lane = threadIdx.x & 31;
    int token = blockIdx.x * 8 + w;
    if (lane == 0) s_cnt[w] = 0;
    __syncwarp();

    unsigned long long v[16];
    unsigned long long m = ~0ull;
#pragma unroll
    for (int i = 0; i < 16; i++) {
        v[i] = g_part[(size_t)token * 512 + i * 32 + lane];
        m = u64min(m, v[i]);
    }
#pragma unroll
    for (int x = 16; x; x >>= 1) {
        unsigned long long o = __shfl_xor_sync(0xFFFFFFFFu, m, x);
        m = u64min(m, o);
    }
    unsigned ub = (unsigned)(m >> 32);
    float dbest = (ub & 0x80000000u) ? __uint_as_float(ub & 0x7FFFFFFFu)
                                     : __uint_as_float(~ub);
    unsigned tb = ordbits(dbest + 0.25f);
#pragma unroll
    for (int i = 0; i < 16; i++) {
        if ((unsigned)(v[i] >> 32) <= tb) {
            int p = atomicAdd(&s_cnt[w], 1);
            if (p < 64) s_code[w][p] = (unsigned)v[i];
        }
    }
    __syncwarp();
    int n = s_cnt[w] < 64 ? s_cnt[w] : 64;

    unsigned winner;
    if (n <= 1) {
        winner = (unsigned)m;
    } else {
        float e[8];
        *(float4*)e       = *(const float4*)(g_enc + (size_t)token * 256 + lane * 8);
        *(float4*)(e + 4) = *(const float4*)(g_enc + (size_t)token * 256 + lane * 8 + 4);
        unsigned long long best = ~0ull;
        for (int s = 0; s < n; s++) {
            unsigned code = s_code[w][s];
            const float* cr = cbk + (size_t)code * 256 + lane * 8;
            float part = 0.f;
#pragma unroll
            for (int j = 0; j < 8; j++) part += e[j] * cr[j];
#pragma unroll
            for (int x = 16; x; x >>= 1) part += __shfl_xor_sync(0xFFFFFFFFu, part, x);
            float d = g_cnorm[code] - 2.f * part;
            unsigned long long p = ((unsigned long long)ordbits(d) << 32) | code;
            best = u64min(best, p);
        }
        winner = (unsigned)best;
    }
    if (lane == 0) {
        g_idx[token] = (int)winner;
        if (out_idx) out_idx[token] = (float)winner;
    }
}

// ---------------- GEMM 3: table = codebook @ w_outT (fp32 FFMA2) ------------
__global__ void __launch_bounds__(256, 2)
gemm_table(const float* __restrict__ cb) {
    __shared__ __align__(16) float As[16 * 128];
    __shared__ __align__(16) float Bs[16 * 128];
    int bx = blockIdx.x, by = blockIdx.y;
    int tid = threadIdx.x, tx = tid & 15, ty = tid >> 4;

    unsigned long long acc[8][4];
#pragma unroll
    for (int i = 0; i < 8; i++)
#pragma unroll
        for (int j = 0; j < 4; j++) acc[i][j] = 0ull;

    const float* Ab = cb + (size_t)(by * 128) * CDIM;
    const float* Bb = g_woutT + bx * 128;

    for (int k0 = 0; k0 < CDIM; k0 += 16) {
#pragma unroll
        for (int it = 0; it < 2; it++) {
            int e  = tid + it * 256;
            int r  = e >> 2;
            int kf = (e & 3) * 4;
            float4 va = *(const float4*)(Ab + (size_t)r * CDIM + k0 + kf);
            As[(kf + 0) * 128 + r] = va.x;
            As[(kf + 1) * 128 + r] = va.y;
            As[(kf + 2) * 128 + r] = va.z;
            As[(kf + 3) * 128 + r] = va.w;
            int k  = e >> 5;
            int n4 = (e & 31) * 4;
            *(float4*)&Bs[k * 128 + n4] = *(const float4*)(Bb + (size_t)(k0 + k) * DDIM + n4);
        }
        __syncthreads();
        mm_step(As, Bs, acc, ty, tx);
        __syncthreads();
    }

    int nbase = bx * 128 + tx * 8;
#pragma unroll
    for (int i = 0; i < 8; i++) {
        int row = by * 128 + ty * 8 + i;
        float* dst = g_table + (size_t)row * DDIM + nbase;
        float2 v0 = upk2(acc[i][0]), v1 = upk2(acc[i][1]);
        float2 v2 = upk2(acc[i][2]), v3 = upk2(acc[i][3]);
        *(float4*)dst       = make_float4(v0.x, v0.y, v1.x, v1.y);
        *(float4*)(dst + 4) = make_float4(v2.x, v2.y, v3.x, v3.y);
    }
}

// ---------------- gather ----------------
__global__ void gather_out(const float* __restrict__ out_b, float* __restrict__ out) {
    int b  = blockIdx.y;
    int t0 = blockIdx.x * 64;
    __shared__ float sm[64][65];
    __shared__ int sidx[64];
    int tid = threadIdx.x;
    if (tid < 64) sidx[tid] = g_idx[b * TDIM + t0 + tid];
    __syncthreads();

    for (int o0 = 0; o0 < DDIM; o0 += 64) {
#pragma unroll
        for (int p = 0; p < 16; p++) {
            int e  = tid + p * 256;
            int tl = e >> 6, ol = e & 63;
            sm[tl][ol] = g_table[(size_t)sidx[tl] * DDIM + o0 + ol];
        }
        __syncthreads();
#pragma unroll
        for (int p = 0; p < 16; p++) {
            int e  = tid + p * 256;
            int ol = e >> 6, tl = e & 63;
            out[(size_t)b * DDIM * TDIM + (size_t)(o0 + ol) * TDIM + t0 + tl] =
                sm[tl][ol] + out_b[o0 + ol];
        }
        __syncthreads();
    }
}

// ---------------- launch ----------------
extern "C" void kernel_launch(void* const* d_in, const int* in_sizes, int n_in,
                              void* d_out, int out_size) {
    const float* z     = (const float*)d_in[0];
    const float* in_v  = (const float*)d_in[1];
    const float* in_g  = (const float*)d_in[2];
    const float* in_b  = (const float*)d_in[3];
    const float* out_v = (const float*)d_in[4];
    const float* out_g = (const float*)d_in[5];
    const float* out_b = (const float*)d_in[6];
    const float* cbk   = (const float*)d_in[7];
    float* out = (float*)d_out;

    cudaFuncSetAttribute(coarse_dist, cudaFuncAttributeMaxDynamicSharedMemorySize, 98304);

    prep_win  <<<256, 256>>>(in_v, in_g);
    prep_wout <<<1024, 256>>>(out_v, out_g);
    prep_cnorm<<<N_CODE, 256>>>(cbk);
    conv_cbH  <<<N_CODE, 256>>>(cbk);

    gemm_ze   <<<dim3(2, 16, BATCH), 256>>>(z, in_b);
    gemm_table<<<dim3(8, 64), 256>>>(cbk);
    coarse_dist<<<dim3(64, 256), 256, 98304>>>();

    const long long out_elems = (long long)BATCH * DDIM * TDIM;
    float* idx_dst = (out_size >= out_elems + M_TOK) ? out + out_elems : nullptr;
    select_k  <<<M_TOK / 8, 256>>>(cbk, idx_dst);

    gather_out<<<dim3(TDIM / 64, BATCH), 256>>>(out_b, out);
}